// round 7
// baseline (speedup 1.0000x reference)
#include <cuda_runtime.h>
#include <cuda_bf16.h>
#include <math.h>
#include <stdint.h>

// Problem constants
#define BB 4
#define SS 1024
#define HH 1024
#define NTOK 4096          // BB*SS
#define NHD 4              // heads
#define HDD 256            // head dim
#define LL 2
#define EE 8
#define FF 4096
#define EHID 2048
#define VV 32000

// ---------------- scratch (device globals; no runtime allocation) ----------------
__device__ float g_x[NTOK * HH];
__device__ float g_qkv[NTOK * 3 * HH];
__device__ float g_scores[BB * NHD * SS * SS];
__device__ float g_attnout[NTOK * HH];
__device__ float g_tmp[NTOK * HH];
__device__ float g_hff[NTOK * FF];
__device__ float g_hmoe[2 * NTOK * EHID];
__device__ float g_ymoe[2 * NTOK * HH];
__device__ int   g_counts[EE];
__device__ int   g_tok[EE * NTOK];
__device__ int   g_slot[EE * NTOK];

// ---------------- helpers ----------------
__device__ __forceinline__ float to_tf32(float x) {
    uint32_t u;
    asm("cvt.rna.tf32.f32 %0, %1;" : "=r"(u) : "f"(x));
    return __uint_as_float(u);
}
__device__ __forceinline__ void split_tf32(float x, float& hi, float& lo) {
    hi = to_tf32(x);
    lo = to_tf32(x - hi);
}
__device__ __forceinline__ void mma_tf32(float* d, const uint32_t* a, const uint32_t* b) {
    asm volatile(
        "mma.sync.aligned.m16n8k8.row.col.f32.tf32.tf32.f32 "
        "{%0,%1,%2,%3}, {%4,%5,%6,%7}, {%8,%9}, {%0,%1,%2,%3};\n"
        : "+f"(d[0]), "+f"(d[1]), "+f"(d[2]), "+f"(d[3])
        : "r"(a[0]), "r"(a[1]), "r"(a[2]), "r"(a[3]), "r"(b[0]), "r"(b[1]));
}

#define TSTR 136              // padded smem row stride
#define TILE_F (16 * TSTR)    // floats per (k16 x 128+pad) tile
#define SMEM_BYTES (4 * 2 * TILE_F * 4)

// ---------------- tensor-core TF32x3 GEMM, 128x128 block tile, K-tile 16 ----------------
// Error-compensated: A,B split into hi/lo tf32; acc += Ah*Bh + Ah*Bl + Al*Bh  (~fp32 accuracy)
// BT=false: B is [K,N] row-major (NN).  BT=true: B is [N,K] row-major (NT).
// z-batching + optional gather/scatter + per-z M (grouped MoE).
// ACT: 0 none, 1 exact GELU, 2 ReLU.
template <bool BT, int ACT>
__global__ void __launch_bounds__(256, 2) gemm_tc(
    int M, int N, int K,
    const float* __restrict__ A, int lda,
    const float* __restrict__ B, int ldb,
    const float* __restrict__ bias,
    float* __restrict__ C, int ldc,
    float alpha, int zdiv,
    long long sAo, long long sAi,
    long long sBo, long long sBi,
    long long sCo, long long sCi,
    long long sBiasO,
    const int* __restrict__ a_rows,
    const int* __restrict__ c_rows,
    int idx_stride,
    const int* __restrict__ Mdev)
{
    int z = blockIdx.z;
    int zo = z / zdiv, zi = z - zo * zdiv;
    A += zo * sAo + zi * sAi;
    B += zo * sBo + zi * sBi;
    C += zo * sCo + zi * sCi;
    if (bias) bias += zo * sBiasO;
    if (Mdev) M = Mdev[z];
    if (a_rows) a_rows += (long long)z * idx_stride;
    if (c_rows) c_rows += (long long)z * idx_stride;

    int bm = blockIdx.y, bn = blockIdx.x;
    if (bm * 128 >= M) return;

    extern __shared__ float smf[];
    float* Ah = smf;
    float* Al = Ah + 2 * TILE_F;
    float* Bh = Al + 2 * TILE_F;
    float* Bl = Bh + 2 * TILE_F;

    int tid  = threadIdx.x;
    int lane = tid & 31, warp = tid >> 5;
    int g = lane >> 2, tg = lane & 3;
    int wm = warp & 3, wn = warp >> 2;   // 4 m-warps x 2 n-warps
    int m0 = wm * 32, n0 = wn * 64;

    // ---- global load setup (2 float4 per thread per operand per K-tile) ----
    long long aoff[2]; bool aok[2]; int arow[2], akc[2];
#pragma unroll
    for (int i = 0; i < 2; i++) {
        int idx = tid + i * 256;
        arow[i] = idx >> 2;
        akc[i]  = (idx & 3) << 2;
        int gr = bm * 128 + arow[i];
        aok[i] = gr < M;
        long long r = 0;
        if (aok[i]) r = a_rows ? (long long)a_rows[gr] : gr;
        aoff[i] = r * (long long)lda;
    }
    long long boff[2]; int bk[2], bc[2];
#pragma unroll
    for (int i = 0; i < 2; i++) {
        int idx = tid + i * 256;
        if (BT) {
            bk[i] = (idx & 3) << 2;  // k within tile
            bc[i] = idx >> 2;        // n row
            boff[i] = (long long)(bn * 128 + bc[i]) * ldb + bk[i];
        } else {
            bk[i] = idx >> 5;            // k row
            bc[i] = (idx & 31) << 2;     // n col
            boff[i] = (long long)bk[i] * ldb + bn * 128 + bc[i];
        }
    }

    float4 ra[2], rb[2];
    auto ldg = [&](int kt) {
#pragma unroll
        for (int i = 0; i < 2; i++) {
            ra[i] = aok[i] ? *(const float4*)(A + aoff[i] + kt + akc[i])
                           : make_float4(0.f, 0.f, 0.f, 0.f);
            rb[i] = BT ? *(const float4*)(B + boff[i] + kt)
                       : *(const float4*)(B + boff[i] + (long long)kt * ldb);
        }
    };
    auto sts = [&](int buf) {
#pragma unroll
        for (int i = 0; i < 2; i++) {
            float av[4] = {ra[i].x, ra[i].y, ra[i].z, ra[i].w};
#pragma unroll
            for (int j = 0; j < 4; j++) {
                float hi, lo; split_tf32(av[j], hi, lo);
                Ah[buf * TILE_F + (akc[i] + j) * TSTR + arow[i]] = hi;
                Al[buf * TILE_F + (akc[i] + j) * TSTR + arow[i]] = lo;
            }
            float bv[4] = {rb[i].x, rb[i].y, rb[i].z, rb[i].w};
            if (BT) {
#pragma unroll
                for (int j = 0; j < 4; j++) {
                    float hi, lo; split_tf32(bv[j], hi, lo);
                    Bh[buf * TILE_F + (bk[i] + j) * TSTR + bc[i]] = hi;
                    Bl[buf * TILE_F + (bk[i] + j) * TSTR + bc[i]] = lo;
                }
            } else {
                float h4[4], l4[4];
#pragma unroll
                for (int j = 0; j < 4; j++) split_tf32(bv[j], h4[j], l4[j]);
                *(float4*)&Bh[buf * TILE_F + bk[i] * TSTR + bc[i]] =
                    make_float4(h4[0], h4[1], h4[2], h4[3]);
                *(float4*)&Bl[buf * TILE_F + bk[i] * TSTR + bc[i]] =
                    make_float4(l4[0], l4[1], l4[2], l4[3]);
            }
        }
    };

    float acc[2][8][4];
#pragma unroll
    for (int mt = 0; mt < 2; mt++)
#pragma unroll
        for (int nt = 0; nt < 8; nt++)
#pragma unroll
            for (int r = 0; r < 4; r++) acc[mt][nt][r] = 0.f;

    ldg(0);
    sts(0);
    __syncthreads();

    int nk = K >> 4;
    for (int t = 0; t < nk; t++) {
        int buf = t & 1;
        bool more = (t + 1 < nk);
        if (more) ldg((t + 1) << 4);

#pragma unroll
        for (int kc = 0; kc < 16; kc += 8) {
            uint32_t afh[2][4], afl[2][4], bfh[8][2], bfl[8][2];
#pragma unroll
            for (int mt = 0; mt < 2; mt++) {
                int r0 = buf * TILE_F + (kc + tg) * TSTR + m0 + mt * 16 + g;
                int r1 = buf * TILE_F + (kc + tg + 4) * TSTR + m0 + mt * 16 + g;
                afh[mt][0] = __float_as_uint(Ah[r0]);
                afh[mt][1] = __float_as_uint(Ah[r0 + 8]);
                afh[mt][2] = __float_as_uint(Ah[r1]);
                afh[mt][3] = __float_as_uint(Ah[r1 + 8]);
                afl[mt][0] = __float_as_uint(Al[r0]);
                afl[mt][1] = __float_as_uint(Al[r0 + 8]);
                afl[mt][2] = __float_as_uint(Al[r1]);
                afl[mt][3] = __float_as_uint(Al[r1 + 8]);
            }
#pragma unroll
            for (int nt = 0; nt < 8; nt++) {
                int c0 = buf * TILE_F + (kc + tg) * TSTR + n0 + nt * 8 + g;
                int c1 = buf * TILE_F + (kc + tg + 4) * TSTR + n0 + nt * 8 + g;
                bfh[nt][0] = __float_as_uint(Bh[c0]);
                bfh[nt][1] = __float_as_uint(Bh[c1]);
                bfl[nt][0] = __float_as_uint(Bl[c0]);
                bfl[nt][1] = __float_as_uint(Bl[c1]);
            }
#pragma unroll
            for (int mt = 0; mt < 2; mt++)
#pragma unroll
                for (int nt = 0; nt < 8; nt++) {
                    mma_tf32(acc[mt][nt], afh[mt], bfl[nt]);
                    mma_tf32(acc[mt][nt], afl[mt], bfh[nt]);
                    mma_tf32(acc[mt][nt], afh[mt], bfh[nt]);
                }
        }

        if (more) sts(buf ^ 1);
        __syncthreads();
    }

    // ---- epilogue ----
#pragma unroll
    for (int mt = 0; mt < 2; mt++) {
#pragma unroll
        for (int h = 0; h < 2; h++) {
            int gm = bm * 128 + m0 + mt * 16 + h * 8 + g;
            if (gm >= M) continue;
            long long crow = c_rows ? (long long)c_rows[gm] : gm;
            float* Cr = C + crow * (long long)ldc + bn * 128 + n0;
            const float* br = bias ? bias + bn * 128 + n0 : nullptr;
#pragma unroll
            for (int nt = 0; nt < 8; nt++) {
                int cb = nt * 8 + 2 * tg;
                float v0 = acc[mt][nt][h * 2 + 0] * alpha;
                float v1 = acc[mt][nt][h * 2 + 1] * alpha;
                if (bias) { v0 += br[cb]; v1 += br[cb + 1]; }
                if (ACT == 1) {
                    v0 = 0.5f * v0 * (1.f + erff(v0 * 0.70710678118654752f));
                    v1 = 0.5f * v1 * (1.f + erff(v1 * 0.70710678118654752f));
                } else if (ACT == 2) {
                    v0 = fmaxf(v0, 0.f);
                    v1 = fmaxf(v1, 0.f);
                }
                *(float2*)(Cr + cb) = make_float2(v0, v1);
            }
        }
    }
}

// ---------------- block reductions ----------------
__device__ __forceinline__ float blkSum(float v, float* red) {
    __syncthreads();
    int lane = threadIdx.x & 31, w = threadIdx.x >> 5;
#pragma unroll
    for (int o = 16; o; o >>= 1) v += __shfl_down_sync(0xffffffffu, v, o);
    if (lane == 0) red[w] = v;
    __syncthreads();
    if (threadIdx.x == 0) {
        float s = 0.f;
        int nw = blockDim.x >> 5;
        for (int i = 0; i < nw; i++) s += red[i];
        red[0] = s;
    }
    __syncthreads();
    return red[0];
}

__device__ __forceinline__ float blkMax(float v, float* red) {
    __syncthreads();
    int lane = threadIdx.x & 31, w = threadIdx.x >> 5;
#pragma unroll
    for (int o = 16; o; o >>= 1) v = fmaxf(v, __shfl_down_sync(0xffffffffu, v, o));
    if (lane == 0) red[w] = v;
    __syncthreads();
    if (threadIdx.x == 0) {
        float s = red[0];
        int nw = blockDim.x >> 5;
        for (int i = 1; i < nw; i++) s = fmaxf(s, red[i]);
        red[0] = s;
    }
    __syncthreads();
    return red[0];
}

// ---------------- small kernels ----------------
__global__ void embed_k(const int* __restrict__ ids,
                        const float* __restrict__ emb,
                        float* __restrict__ x) {
    int t = blockIdx.x;
    int c = threadIdx.x;
    ((float4*)x)[(long long)t * 256 + c] =
        ((const float4*)emb)[(long long)ids[t] * 256 + c];
}

__global__ void softmax_k(float* __restrict__ s) {
    __shared__ float red[32];
    long long base = (long long)blockIdx.x * 1024;
    float4* p = (float4*)(s + base);
    float4 v = p[threadIdx.x];
    float m = fmaxf(fmaxf(v.x, v.y), fmaxf(v.z, v.w));
    m = blkMax(m, red);
    v.x = __expf(v.x - m); v.y = __expf(v.y - m);
    v.z = __expf(v.z - m); v.w = __expf(v.w - m);
    float sum = blkSum(v.x + v.y + v.z + v.w, red);
    float inv = 1.f / sum;
    v.x *= inv; v.y *= inv; v.z *= inv; v.w *= inv;
    p[threadIdx.x] = v;
}

// x = LayerNorm(x + res) * g + b
__global__ void ln_res_k(float* __restrict__ x, const float* __restrict__ res,
                         const float* __restrict__ g, const float* __restrict__ b) {
    __shared__ float sh[1024];
    __shared__ float red[32];
    long long base = (long long)blockIdx.x * 1024;
    int tid = threadIdx.x;
    float s = 0.f, s2 = 0.f;
    for (int i = tid; i < 1024; i += 256) {
        float v = x[base + i] + res[base + i];
        sh[i] = v; s += v; s2 += v * v;
    }
    float mean = blkSum(s, red) * (1.f / 1024.f);
    float msq  = blkSum(s2, red) * (1.f / 1024.f);
    float inv = rsqrtf(msq - mean * mean + 1e-5f);
    for (int i = tid; i < 1024; i += 256)
        x[base + i] = (sh[i] - mean) * inv * g[i] + b[i];
}

__global__ void zero_counts_k(int* c) { c[threadIdx.x] = 0; }

// one block per token; 8 warps, warp w computes gate logit for expert w
__global__ void gate_topk_k(const float* __restrict__ x,
                            const float* __restrict__ gw,  // [H, E]
                            const float* __restrict__ gb,  // [E]
                            int* __restrict__ counts,
                            int* __restrict__ tok,
                            int* __restrict__ slot) {
    int t = blockIdx.x;
    int tid = threadIdx.x;
    int w = tid >> 5, lane = tid & 31;
    const float* xr = x + (long long)t * HH;
    float s = 0.f;
    for (int k = lane; k < HH; k += 32) s += xr[k] * gw[k * EE + w];
#pragma unroll
    for (int o = 16; o; o >>= 1) s += __shfl_down_sync(0xffffffffu, s, o);
    __shared__ float logits[EE];
    if (lane == 0) logits[w] = s + gb[w];
    __syncthreads();
    if (tid == 0) {
        int i1 = 0; float m1 = logits[0];
        for (int e = 1; e < EE; e++) if (logits[e] > m1) { m1 = logits[e]; i1 = e; }
        int i2 = -1; float m2 = -3.0e38f;
        for (int e = 0; e < EE; e++) if (e != i1 && logits[e] > m2) { m2 = logits[e]; i2 = e; }
        int p = atomicAdd(&counts[i1], 1);
        tok[i1 * NTOK + p] = t; slot[i1 * NTOK + p] = 2 * t;
        p = atomicAdd(&counts[i2], 1);
        tok[i2 * NTOK + p] = t; slot[i2 * NTOK + p] = 2 * t + 1;
    }
}

// x[t] = ymoe[2t] + ymoe[2t+1]
__global__ void moe_combine_k(float* __restrict__ x, const float* __restrict__ y) {
    int t = blockIdx.x, c = threadIdx.x;
    const float4* y4 = (const float4*)y;
    float4 u = y4[(long long)(2 * t) * 256 + c];
    float4 v = y4[(long long)(2 * t + 1) * 256 + c];
    float4 o;
    o.x = u.x + v.x; o.y = u.y + v.y; o.z = u.z + v.z; o.w = u.w + v.w;
    ((float4*)x)[(long long)t * 256 + c] = o;
}

// ---------------- host launch ----------------
extern "C" void kernel_launch(void* const* d_in, const int* in_sizes, int n_in,
                              void* d_out, int out_size) {
    const int*   ids   = (const int*)d_in[0];
    const float* embw  = (const float*)d_in[1];
    const float* qkvw  = (const float*)d_in[2];
    const float* qkvb  = (const float*)d_in[3];
    const float* outw  = (const float*)d_in[4];
    const float* outb  = (const float*)d_in[5];
    const float* ln1g  = (const float*)d_in[6];
    const float* ln1b  = (const float*)d_in[7];
    const float* ffw1  = (const float*)d_in[8];
    const float* ffb1  = (const float*)d_in[9];
    const float* ffw2  = (const float*)d_in[10];
    const float* ffb2  = (const float*)d_in[11];
    const float* ln2g  = (const float*)d_in[12];
    const float* ln2b  = (const float*)d_in[13];
    const float* gatew = (const float*)d_in[14];
    const float* gateb = (const float*)d_in[15];
    const float* ew1   = (const float*)d_in[16];
    const float* eb1   = (const float*)d_in[17];
    const float* ew2   = (const float*)d_in[18];
    const float* eb2   = (const float*)d_in[19];
    const float* lmw   = (const float*)d_in[20];
    const float* lmb   = (const float*)d_in[21];
    float* out = (float*)d_out;

    float *xb, *qkvB, *scB, *aoB, *tmpB, *hffB, *hmoeB, *ymoeB;
    int *cnt, *tokB, *slotB;
    cudaGetSymbolAddress((void**)&xb, g_x);
    cudaGetSymbolAddress((void**)&qkvB, g_qkv);
    cudaGetSymbolAddress((void**)&scB, g_scores);
    cudaGetSymbolAddress((void**)&aoB, g_attnout);
    cudaGetSymbolAddress((void**)&tmpB, g_tmp);
    cudaGetSymbolAddress((void**)&hffB, g_hff);
    cudaGetSymbolAddress((void**)&hmoeB, g_hmoe);
    cudaGetSymbolAddress((void**)&ymoeB, g_ymoe);
    cudaGetSymbolAddress((void**)&cnt, g_counts);
    cudaGetSymbolAddress((void**)&tokB, g_tok);
    cudaGetSymbolAddress((void**)&slotB, g_slot);

    cudaFuncSetAttribute(gemm_tc<true, 0>,  cudaFuncAttributeMaxDynamicSharedMemorySize, SMEM_BYTES);
    cudaFuncSetAttribute(gemm_tc<false, 0>, cudaFuncAttributeMaxDynamicSharedMemorySize, SMEM_BYTES);
    cudaFuncSetAttribute(gemm_tc<false, 1>, cudaFuncAttributeMaxDynamicSharedMemorySize, SMEM_BYTES);
    cudaFuncSetAttribute(gemm_tc<false, 2>, cudaFuncAttributeMaxDynamicSharedMemorySize, SMEM_BYTES);

    embed_k<<<NTOK, 256>>>(ids, embw, xb);

    for (int l = 0; l < LL; l++) {
        // --- QKV projection (x @ Wqkv^T + b): NT, M=4096 N=3072 K=1024 ---
        gemm_tc<true, 0><<<dim3(24, 32, 1), 256, SMEM_BYTES>>>(
            NTOK, 3 * HH, HH, xb, HH,
            qkvw + (long long)l * 3 * HH * HH, HH, qkvb + l * 3 * HH,
            qkvB, 3 * HH, 1.f, 1, 0, 0, 0, 0, 0, 0, 0,
            nullptr, nullptr, 0, nullptr);

        // --- scores = Q @ K^T / 16, batched over (b,h): z=16 ---
        gemm_tc<true, 0><<<dim3(8, 8, 16), 256, SMEM_BYTES>>>(
            SS, SS, HDD, qkvB, 3 * HH, qkvB + HH, 3 * HH, nullptr,
            scB, SS, 0.0625f, NHD,
            (long long)SS * 3 * HH, HDD,
            (long long)SS * 3 * HH, HDD,
            (long long)NHD * SS * SS, (long long)SS * SS,
            0, nullptr, nullptr, 0, nullptr);

        softmax_k<<<BB * NHD * SS, 256>>>(scB);

        // --- AO = P @ V, batched over (b,h): NN, M=1024 N=256 K=1024 ---
        gemm_tc<false, 0><<<dim3(2, 8, 16), 256, SMEM_BYTES>>>(
            SS, HDD, SS, scB, SS, qkvB + 2 * HH, 3 * HH, nullptr,
            aoB, HH, 1.f, NHD,
            (long long)NHD * SS * SS, (long long)SS * SS,
            (long long)SS * 3 * HH, HDD,
            (long long)SS * HH, HDD,
            0, nullptr, nullptr, 0, nullptr);

        // --- out projection (ao @ Wout^T + b): NT ---
        gemm_tc<true, 0><<<dim3(8, 32, 1), 256, SMEM_BYTES>>>(
            NTOK, HH, HH, aoB, HH,
            outw + (long long)l * HH * HH, HH, outb + l * HH,
            tmpB, HH, 1.f, 1, 0, 0, 0, 0, 0, 0, 0,
            nullptr, nullptr, 0, nullptr);

        ln_res_k<<<NTOK, 256>>>(xb, tmpB, ln1g + l * HH, ln1b + l * HH);

        // --- FFN stage 1 (GELU fused): NN, N=4096 ---
        gemm_tc<false, 1><<<dim3(32, 32, 1), 256, SMEM_BYTES>>>(
            NTOK, FF, HH, xb, HH,
            ffw1 + (long long)l * HH * FF, FF, ffb1 + l * FF,
            hffB, FF, 1.f, 1, 0, 0, 0, 0, 0, 0, 0,
            nullptr, nullptr, 0, nullptr);

        // --- FFN stage 2: NN, K=4096 ---
        gemm_tc<false, 0><<<dim3(8, 32, 1), 256, SMEM_BYTES>>>(
            NTOK, HH, FF, hffB, FF,
            ffw2 + (long long)l * FF * HH, HH, ffb2 + l * HH,
            tmpB, HH, 1.f, 1, 0, 0, 0, 0, 0, 0, 0,
            nullptr, nullptr, 0, nullptr);

        ln_res_k<<<NTOK, 256>>>(xb, tmpB, ln2g + l * HH, ln2b + l * HH);

        // --- MoE routing: top-2 of 8 ---
        zero_counts_k<<<1, EE>>>(cnt);
        gate_topk_k<<<NTOK, 256>>>(xb, gatew + (long long)l * HH * EE,
                                   gateb + l * EE, cnt, tokB, slotB);

        // --- MoE stage 1 (gathered rows, ReLU fused): per-expert grouped GEMM ---
        gemm_tc<false, 2><<<dim3(16, 32, 8), 256, SMEM_BYTES>>>(
            NTOK, EHID, HH, xb, HH,
            ew1 + (long long)l * EE * HH * EHID, EHID,
            eb1 + (long long)l * EE * EHID,
            hmoeB, EHID, 1.f, 1,
            0, 0, (long long)HH * EHID, 0, 0, 0, (long long)EHID,
            tokB, slotB, NTOK, cnt);

        // --- MoE stage 2: per-expert grouped GEMM ---
        gemm_tc<false, 0><<<dim3(8, 32, 8), 256, SMEM_BYTES>>>(
            NTOK, HH, EHID, hmoeB, EHID,
            ew2 + (long long)l * EE * EHID * HH, HH,
            eb2 + (long long)l * EE * HH,
            ymoeB, HH, 1.f, 1,
            0, 0, (long long)EHID * HH, 0, 0, 0, (long long)HH,
            slotB, slotB, NTOK, cnt);

        moe_combine_k<<<NTOK, 256>>>(xb, ymoeB);
    }

    // --- LM head: NN, M=4096 N=32000 K=1024 ---
    gemm_tc<false, 0><<<dim3(250, 32, 1), 256, SMEM_BYTES>>>(
        NTOK, VV, HH, xb, HH, lmw, VV, lmb,
        out, VV, 1.f, 1, 0, 0, 0, 0, 0, 0, 0,
        nullptr, nullptr, 0, nullptr);
}

// round 8
// speedup vs baseline: 1.1640x; 1.1640x over previous
#include <cuda_runtime.h>
#include <cuda_bf16.h>
#include <math.h>
#include <stdint.h>

// Problem constants
#define BB 4
#define SS 1024
#define HH 1024
#define NTOK 4096          // BB*SS
#define NHD 4              // heads
#define HDD 256            // head dim
#define LL 2
#define EE 8
#define FF 4096
#define EHID 2048
#define VV 32000

// ---------------- scratch (device globals; no runtime allocation) ----------------
__device__ float g_x[NTOK * HH];
__device__ float g_qkv[NTOK * 3 * HH];
__device__ float g_scores[BB * NHD * SS * SS];
__device__ float g_attnout[NTOK * HH];
__device__ float g_tmp[NTOK * HH];
__device__ float g_hff[NTOK * FF];
__device__ float g_hmoe[2 * NTOK * EHID];
__device__ float g_ymoe[2 * NTOK * HH];
__device__ int   g_counts[EE];
__device__ int   g_tok[EE * NTOK];
__device__ int   g_slot[EE * NTOK];

// ---------------- helpers ----------------
__device__ __forceinline__ float to_tf32(float x) {
    uint32_t u;
    asm("cvt.rna.tf32.f32 %0, %1;" : "=r"(u) : "f"(x));
    return __uint_as_float(u);
}
__device__ __forceinline__ void mma_tf32(float* d, const uint32_t* a, const uint32_t* b) {
    asm volatile(
        "mma.sync.aligned.m16n8k8.row.col.f32.tf32.tf32.f32 "
        "{%0,%1,%2,%3}, {%4,%5,%6,%7}, {%8,%9}, {%0,%1,%2,%3};\n"
        : "+f"(d[0]), "+f"(d[1]), "+f"(d[2]), "+f"(d[3])
        : "r"(a[0]), "r"(a[1]), "r"(a[2]), "r"(a[3]), "r"(b[0]), "r"(b[1]));
}
__device__ __forceinline__ void cp_async16(uint32_t dst, const void* src, bool pred) {
    int sz = pred ? 16 : 0;
    asm volatile("cp.async.cg.shared.global [%0], [%1], 16, %2;\n"
                 :: "r"(dst), "l"(src), "r"(sz));
}
__device__ __forceinline__ void cp_commit() { asm volatile("cp.async.commit_group;\n"); }
template <int N> __device__ __forceinline__ void cp_wait() {
    asm volatile("cp.async.wait_group %0;\n" :: "n"(N));
}

// smem tile geometry (fp32 tiles; split to tf32 hi/lo at fragment-load time)
#define A_STRIDE 20                 // [m(128)][k(16)] padded rows (bank-bijective)
#define B_STRIDE_NN 136             // [k(16)][n(128)] padded rows
#define ASTG (128 * A_STRIDE)       // 2560 floats
#define BSTG 2560                   // max(16*136=2176, 128*20=2560)
#define STG_F (ASTG + BSTG)         // 5120 floats per stage
#define NSTAGE 5
#define SMEM_BYTES (NSTAGE * STG_F * 4)   // 102400 B

// ---------------- tensor-core TF32x3 GEMM, 128x128 tile, K-tile 16, cp.async x5 ----------------
// Error-compensated: acc += Ah*Bh + Al*Bh (+ Ah*Bl when NMMA==3)
// BT=false: B is [K,N] row-major (NN).  BT=true: B is [N,K] row-major (NT).
// z-batching + optional gather/scatter + per-z M (grouped MoE).
// ACT: 0 none, 1 exact GELU, 2 ReLU.  NMMA: 3 (full) or 2 (drop B-lo term).
template <bool BT, int ACT, int NMMA>
__global__ void __launch_bounds__(256, 2) gemm_tc(
    int M, int N, int K,
    const float* __restrict__ A, int lda,
    const float* __restrict__ B, int ldb,
    const float* __restrict__ bias,
    float* __restrict__ C, int ldc,
    float alpha, int zdiv,
    long long sAo, long long sAi,
    long long sBo, long long sBi,
    long long sCo, long long sCi,
    long long sBiasO,
    const int* __restrict__ a_rows,
    const int* __restrict__ c_rows,
    int idx_stride,
    const int* __restrict__ Mdev)
{
    int z = blockIdx.z;
    int zo = z / zdiv, zi = z - zo * zdiv;
    A += zo * sAo + zi * sAi;
    B += zo * sBo + zi * sBi;
    C += zo * sCo + zi * sCi;
    if (bias) bias += zo * sBiasO;
    if (Mdev) M = Mdev[z];
    if (a_rows) a_rows += (long long)z * idx_stride;
    if (c_rows) c_rows += (long long)z * idx_stride;

    int bm = blockIdx.y, bn = blockIdx.x;
    if (bm * 128 >= M) return;

    extern __shared__ float smf[];
    uint32_t smem_u32 = (uint32_t)__cvta_generic_to_shared(smf);

    int tid  = threadIdx.x;
    int lane = tid & 31, warp = tid >> 5;
    int g = lane >> 2, tg = lane & 3;
    int wm = warp & 3, wn = warp >> 2;   // 4 m-warps x 2 n-warps
    int m0 = wm * 32, n0 = wn * 64;

    // ---- cp.async source/dest setup (2 x 16B per operand per thread per K-tile) ----
    const float* asrc[2]; bool aok[2]; uint32_t adst[2];
#pragma unroll
    for (int i = 0; i < 2; i++) {
        int idx = tid + i * 256;
        int arow = idx >> 2;
        int akc  = (idx & 3) << 2;
        int gr = bm * 128 + arow;
        aok[i] = gr < M;
        long long r = 0;
        if (aok[i]) r = a_rows ? (long long)a_rows[gr] : gr;
        asrc[i] = A + r * (long long)lda + akc;
        adst[i] = (uint32_t)((arow * A_STRIDE + akc) * 4);
    }
    const float* bsrc[2]; uint32_t bdst[2];
#pragma unroll
    for (int i = 0; i < 2; i++) {
        int idx = tid + i * 256;
        if (BT) {
            int brow = idx >> 2;          // n
            int bkc  = (idx & 3) << 2;    // k
            bsrc[i] = B + (long long)(bn * 128 + brow) * ldb + bkc;
            bdst[i] = (uint32_t)((ASTG + brow * A_STRIDE + bkc) * 4);
        } else {
            int bkr = idx >> 5;           // k
            int bnc = (idx & 31) << 2;    // n
            bsrc[i] = B + (long long)bkr * ldb + bn * 128 + bnc;
            bdst[i] = (uint32_t)((ASTG + bkr * B_STRIDE_NN + bnc) * 4);
        }
    }

    auto issue = [&](int t) {
        int kt = t << 4;
        uint32_t sb = smem_u32 + (uint32_t)((t % NSTAGE) * STG_F * 4);
#pragma unroll
        for (int i = 0; i < 2; i++) {
            cp_async16(sb + adst[i], asrc[i] + kt, aok[i]);
            const float* bs = BT ? (bsrc[i] + kt)
                                 : (bsrc[i] + (long long)kt * ldb);
            cp_async16(sb + bdst[i], bs, true);
        }
        cp_commit();
    };

    float acc[2][8][4];
#pragma unroll
    for (int mt = 0; mt < 2; mt++)
#pragma unroll
        for (int nt = 0; nt < 8; nt++)
#pragma unroll
            for (int r = 0; r < 4; r++) acc[mt][nt][r] = 0.f;

    int nk = K >> 4;
    issue(0); issue(1); issue(2);   // K >= 256 always -> nk >= 16

    for (int t = 0; t < nk; t++) {
        if (t + 3 < nk) issue(t + 3); else cp_commit();  // keep group count advancing
        cp_wait<2>();
        __syncthreads();

        const float* As = smf + (t % NSTAGE) * STG_F;
        const float* Bs = As + ASTG;

#pragma unroll
        for (int kc = 0; kc < 16; kc += 8) {
            uint32_t afh[2][4], afl[2][4], bfh[8][2], bfl[8][2];
#pragma unroll
            for (int mt = 0; mt < 2; mt++) {
                int mb = (m0 + mt * 16 + g) * A_STRIDE + kc + tg;
                float r0 = As[mb], r1 = As[mb + 8 * A_STRIDE];
                float r2 = As[mb + 4], r3 = As[mb + 8 * A_STRIDE + 4];
                float h;
                h = to_tf32(r0); afh[mt][0] = __float_as_uint(h); afl[mt][0] = __float_as_uint(to_tf32(r0 - h));
                h = to_tf32(r1); afh[mt][1] = __float_as_uint(h); afl[mt][1] = __float_as_uint(to_tf32(r1 - h));
                h = to_tf32(r2); afh[mt][2] = __float_as_uint(h); afl[mt][2] = __float_as_uint(to_tf32(r2 - h));
                h = to_tf32(r3); afh[mt][3] = __float_as_uint(h); afl[mt][3] = __float_as_uint(to_tf32(r3 - h));
            }
#pragma unroll
            for (int nt = 0; nt < 8; nt++) {
                float b0, b1;
                if (BT) {
                    int nb = (n0 + nt * 8 + g) * A_STRIDE + kc + tg;
                    b0 = Bs[nb]; b1 = Bs[nb + 4];
                } else {
                    int nb = (kc + tg) * B_STRIDE_NN + n0 + nt * 8 + g;
                    b0 = Bs[nb]; b1 = Bs[nb + 4 * B_STRIDE_NN];
                }
                float h;
                h = to_tf32(b0); bfh[nt][0] = __float_as_uint(h);
                if (NMMA == 3) bfl[nt][0] = __float_as_uint(to_tf32(b0 - h));
                h = to_tf32(b1); bfh[nt][1] = __float_as_uint(h);
                if (NMMA == 3) bfl[nt][1] = __float_as_uint(to_tf32(b1 - h));
            }
#pragma unroll
            for (int mt = 0; mt < 2; mt++)
#pragma unroll
                for (int nt = 0; nt < 8; nt++) {
                    if (NMMA == 3) mma_tf32(acc[mt][nt], afh[mt], bfl[nt]);
                    mma_tf32(acc[mt][nt], afl[mt], bfh[nt]);
                    mma_tf32(acc[mt][nt], afh[mt], bfh[nt]);
                }
        }
        __syncthreads();
    }

    // ---- epilogue ----
#pragma unroll
    for (int mt = 0; mt < 2; mt++) {
#pragma unroll
        for (int h = 0; h < 2; h++) {
            int gm = bm * 128 + m0 + mt * 16 + h * 8 + g;
            if (gm >= M) continue;
            long long crow = c_rows ? (long long)c_rows[gm] : gm;
            float* Cr = C + crow * (long long)ldc + bn * 128 + n0;
            const float* br = bias ? bias + bn * 128 + n0 : nullptr;
#pragma unroll
            for (int nt = 0; nt < 8; nt++) {
                int cb = nt * 8 + 2 * tg;
                float v0 = acc[mt][nt][h * 2 + 0] * alpha;
                float v1 = acc[mt][nt][h * 2 + 1] * alpha;
                if (bias) { v0 += br[cb]; v1 += br[cb + 1]; }
                if (ACT == 1) {
                    v0 = 0.5f * v0 * (1.f + erff(v0 * 0.70710678118654752f));
                    v1 = 0.5f * v1 * (1.f + erff(v1 * 0.70710678118654752f));
                } else if (ACT == 2) {
                    v0 = fmaxf(v0, 0.f);
                    v1 = fmaxf(v1, 0.f);
                }
                *(float2*)(Cr + cb) = make_float2(v0, v1);
            }
        }
    }
}

// ---------------- block reductions ----------------
__device__ __forceinline__ float blkSum(float v, float* red) {
    __syncthreads();
    int lane = threadIdx.x & 31, w = threadIdx.x >> 5;
#pragma unroll
    for (int o = 16; o; o >>= 1) v += __shfl_down_sync(0xffffffffu, v, o);
    if (lane == 0) red[w] = v;
    __syncthreads();
    if (threadIdx.x == 0) {
        float s = 0.f;
        int nw = blockDim.x >> 5;
        for (int i = 0; i < nw; i++) s += red[i];
        red[0] = s;
    }
    __syncthreads();
    return red[0];
}

__device__ __forceinline__ float blkMax(float v, float* red) {
    __syncthreads();
    int lane = threadIdx.x & 31, w = threadIdx.x >> 5;
#pragma unroll
    for (int o = 16; o; o >>= 1) v = fmaxf(v, __shfl_down_sync(0xffffffffu, v, o));
    if (lane == 0) red[w] = v;
    __syncthreads();
    if (threadIdx.x == 0) {
        float s = red[0];
        int nw = blockDim.x >> 5;
        for (int i = 1; i < nw; i++) s = fmaxf(s, red[i]);
        red[0] = s;
    }
    __syncthreads();
    return red[0];
}

// ---------------- small kernels ----------------
__global__ void embed_k(const int* __restrict__ ids,
                        const float* __restrict__ emb,
                        float* __restrict__ x) {
    int t = blockIdx.x;
    int c = threadIdx.x;
    ((float4*)x)[(long long)t * 256 + c] =
        ((const float4*)emb)[(long long)ids[t] * 256 + c];
}

__global__ void softmax_k(float* __restrict__ s) {
    __shared__ float red[32];
    long long base = (long long)blockIdx.x * 1024;
    float4* p = (float4*)(s + base);
    float4 v = p[threadIdx.x];
    float m = fmaxf(fmaxf(v.x, v.y), fmaxf(v.z, v.w));
    m = blkMax(m, red);
    v.x = __expf(v.x - m); v.y = __expf(v.y - m);
    v.z = __expf(v.z - m); v.w = __expf(v.w - m);
    float sum = blkSum(v.x + v.y + v.z + v.w, red);
    float inv = 1.f / sum;
    v.x *= inv; v.y *= inv; v.z *= inv; v.w *= inv;
    p[threadIdx.x] = v;
}

// x = LayerNorm(x + res) * g + b
__global__ void ln_res_k(float* __restrict__ x, const float* __restrict__ res,
                         const float* __restrict__ g, const float* __restrict__ b) {
    __shared__ float sh[1024];
    __shared__ float red[32];
    long long base = (long long)blockIdx.x * 1024;
    int tid = threadIdx.x;
    float s = 0.f, s2 = 0.f;
    for (int i = tid; i < 1024; i += 256) {
        float v = x[base + i] + res[base + i];
        sh[i] = v; s += v; s2 += v * v;
    }
    float mean = blkSum(s, red) * (1.f / 1024.f);
    float msq  = blkSum(s2, red) * (1.f / 1024.f);
    float inv = rsqrtf(msq - mean * mean + 1e-5f);
    for (int i = tid; i < 1024; i += 256)
        x[base + i] = (sh[i] - mean) * inv * g[i] + b[i];
}

__global__ void zero_counts_k(int* c) { c[threadIdx.x] = 0; }

// one block per token; 8 warps, warp w computes gate logit for expert w
__global__ void gate_topk_k(const float* __restrict__ x,
                            const float* __restrict__ gw,  // [H, E]
                            const float* __restrict__ gb,  // [E]
                            int* __restrict__ counts,
                            int* __restrict__ tok,
                            int* __restrict__ slot) {
    int t = blockIdx.x;
    int tid = threadIdx.x;
    int w = tid >> 5, lane = tid & 31;
    const float* xr = x + (long long)t * HH;
    float s = 0.f;
    for (int k = lane; k < HH; k += 32) s += xr[k] * gw[k * EE + w];
#pragma unroll
    for (int o = 16; o; o >>= 1) s += __shfl_down_sync(0xffffffffu, s, o);
    __shared__ float logits[EE];
    if (lane == 0) logits[w] = s + gb[w];
    __syncthreads();
    if (tid == 0) {
        int i1 = 0; float m1 = logits[0];
        for (int e = 1; e < EE; e++) if (logits[e] > m1) { m1 = logits[e]; i1 = e; }
        int i2 = -1; float m2 = -3.0e38f;
        for (int e = 0; e < EE; e++) if (e != i1 && logits[e] > m2) { m2 = logits[e]; i2 = e; }
        int p = atomicAdd(&counts[i1], 1);
        tok[i1 * NTOK + p] = t; slot[i1 * NTOK + p] = 2 * t;
        p = atomicAdd(&counts[i2], 1);
        tok[i2 * NTOK + p] = t; slot[i2 * NTOK + p] = 2 * t + 1;
    }
}

// x[t] = ymoe[2t] + ymoe[2t+1]
__global__ void moe_combine_k(float* __restrict__ x, const float* __restrict__ y) {
    int t = blockIdx.x, c = threadIdx.x;
    const float4* y4 = (const float4*)y;
    float4 u = y4[(long long)(2 * t) * 256 + c];
    float4 v = y4[(long long)(2 * t + 1) * 256 + c];
    float4 o;
    o.x = u.x + v.x; o.y = u.y + v.y; o.z = u.z + v.z; o.w = u.w + v.w;
    ((float4*)x)[(long long)t * 256 + c] = o;
}

// ---------------- host launch ----------------
extern "C" void kernel_launch(void* const* d_in, const int* in_sizes, int n_in,
                              void* d_out, int out_size) {
    const int*   ids   = (const int*)d_in[0];
    const float* embw  = (const float*)d_in[1];
    const float* qkvw  = (const float*)d_in[2];
    const float* qkvb  = (const float*)d_in[3];
    const float* outw  = (const float*)d_in[4];
    const float* outb  = (const float*)d_in[5];
    const float* ln1g  = (const float*)d_in[6];
    const float* ln1b  = (const float*)d_in[7];
    const float* ffw1  = (const float*)d_in[8];
    const float* ffb1  = (const float*)d_in[9];
    const float* ffw2  = (const float*)d_in[10];
    const float* ffb2  = (const float*)d_in[11];
    const float* ln2g  = (const float*)d_in[12];
    const float* ln2b  = (const float*)d_in[13];
    const float* gatew = (const float*)d_in[14];
    const float* gateb = (const float*)d_in[15];
    const float* ew1   = (const float*)d_in[16];
    const float* eb1   = (const float*)d_in[17];
    const float* ew2   = (const float*)d_in[18];
    const float* eb2   = (const float*)d_in[19];
    const float* lmw   = (const float*)d_in[20];
    const float* lmb   = (const float*)d_in[21];
    float* out = (float*)d_out;

    float *xb, *qkvB, *scB, *aoB, *tmpB, *hffB, *hmoeB, *ymoeB;
    int *cnt, *tokB, *slotB;
    cudaGetSymbolAddress((void**)&xb, g_x);
    cudaGetSymbolAddress((void**)&qkvB, g_qkv);
    cudaGetSymbolAddress((void**)&scB, g_scores);
    cudaGetSymbolAddress((void**)&aoB, g_attnout);
    cudaGetSymbolAddress((void**)&tmpB, g_tmp);
    cudaGetSymbolAddress((void**)&hffB, g_hff);
    cudaGetSymbolAddress((void**)&hmoeB, g_hmoe);
    cudaGetSymbolAddress((void**)&ymoeB, g_ymoe);
    cudaGetSymbolAddress((void**)&cnt, g_counts);
    cudaGetSymbolAddress((void**)&tokB, g_tok);
    cudaGetSymbolAddress((void**)&slotB, g_slot);

    cudaFuncSetAttribute(gemm_tc<true, 0, 3>,  cudaFuncAttributeMaxDynamicSharedMemorySize, SMEM_BYTES);
    cudaFuncSetAttribute(gemm_tc<false, 0, 3>, cudaFuncAttributeMaxDynamicSharedMemorySize, SMEM_BYTES);
    cudaFuncSetAttribute(gemm_tc<false, 1, 3>, cudaFuncAttributeMaxDynamicSharedMemorySize, SMEM_BYTES);
    cudaFuncSetAttribute(gemm_tc<false, 2, 3>, cudaFuncAttributeMaxDynamicSharedMemorySize, SMEM_BYTES);
    cudaFuncSetAttribute(gemm_tc<false, 0, 2>, cudaFuncAttributeMaxDynamicSharedMemorySize, SMEM_BYTES);

    embed_k<<<NTOK, 256>>>(ids, embw, xb);

    for (int l = 0; l < LL; l++) {
        // --- QKV projection (x @ Wqkv^T + b): NT, M=4096 N=3072 K=1024 ---
        gemm_tc<true, 0, 3><<<dim3(24, 32, 1), 256, SMEM_BYTES>>>(
            NTOK, 3 * HH, HH, xb, HH,
            qkvw + (long long)l * 3 * HH * HH, HH, qkvb + l * 3 * HH,
            qkvB, 3 * HH, 1.f, 1, 0, 0, 0, 0, 0, 0, 0,
            nullptr, nullptr, 0, nullptr);

        // --- scores = Q @ K^T / 16, batched over (b,h): z=16 ---
        gemm_tc<true, 0, 3><<<dim3(8, 8, 16), 256, SMEM_BYTES>>>(
            SS, SS, HDD, qkvB, 3 * HH, qkvB + HH, 3 * HH, nullptr,
            scB, SS, 0.0625f, NHD,
            (long long)SS * 3 * HH, HDD,
            (long long)SS * 3 * HH, HDD,
            (long long)NHD * SS * SS, (long long)SS * SS,
            0, nullptr, nullptr, 0, nullptr);

        softmax_k<<<BB * NHD * SS, 256>>>(scB);

        // --- AO = P @ V, batched over (b,h): NN, M=1024 N=256 K=1024 ---
        gemm_tc<false, 0, 3><<<dim3(2, 8, 16), 256, SMEM_BYTES>>>(
            SS, HDD, SS, scB, SS, qkvB + 2 * HH, 3 * HH, nullptr,
            aoB, HH, 1.f, NHD,
            (long long)NHD * SS * SS, (long long)SS * SS,
            (long long)SS * 3 * HH, HDD,
            (long long)SS * HH, HDD,
            0, nullptr, nullptr, 0, nullptr);

        // --- out projection (ao @ Wout^T + b): NT ---
        gemm_tc<true, 0, 3><<<dim3(8, 32, 1), 256, SMEM_BYTES>>>(
            NTOK, HH, HH, aoB, HH,
            outw + (long long)l * HH * HH, HH, outb + l * HH,
            tmpB, HH, 1.f, 1, 0, 0, 0, 0, 0, 0, 0,
            nullptr, nullptr, 0, nullptr);

        ln_res_k<<<NTOK, 256>>>(xb, tmpB, ln1g + l * HH, ln1b + l * HH);

        // --- FFN stage 1 (GELU fused): NN, N=4096 ---
        gemm_tc<false, 1, 3><<<dim3(32, 32, 1), 256, SMEM_BYTES>>>(
            NTOK, FF, HH, xb, HH,
            ffw1 + (long long)l * HH * FF, FF, ffb1 + l * FF,
            hffB, FF, 1.f, 1, 0, 0, 0, 0, 0, 0, 0,
            nullptr, nullptr, 0, nullptr);

        // --- FFN stage 2: NN, K=4096 ---
        gemm_tc<false, 0, 3><<<dim3(8, 32, 1), 256, SMEM_BYTES>>>(
            NTOK, HH, FF, hffB, FF,
            ffw2 + (long long)l * FF * HH, HH, ffb2 + l * HH,
            tmpB, HH, 1.f, 1, 0, 0, 0, 0, 0, 0, 0,
            nullptr, nullptr, 0, nullptr);

        ln_res_k<<<NTOK, 256>>>(xb, tmpB, ln2g + l * HH, ln2b + l * HH);

        // --- MoE routing: top-2 of 8 ---
        zero_counts_k<<<1, EE>>>(cnt);
        gate_topk_k<<<NTOK, 256>>>(xb, gatew + (long long)l * HH * EE,
                                   gateb + l * EE, cnt, tokB, slotB);

        // --- MoE stage 1 (gathered rows, ReLU fused): per-expert grouped GEMM ---
        gemm_tc<false, 2, 3><<<dim3(16, 32, 8), 256, SMEM_BYTES>>>(
            NTOK, EHID, HH, xb, HH,
            ew1 + (long long)l * EE * HH * EHID, EHID,
            eb1 + (long long)l * EE * EHID,
            hmoeB, EHID, 1.f, 1,
            0, 0, (long long)HH * EHID, 0, 0, 0, (long long)EHID,
            tokB, slotB, NTOK, cnt);

        // --- MoE stage 2: per-expert grouped GEMM ---
        gemm_tc<false, 0, 3><<<dim3(8, 32, 8), 256, SMEM_BYTES>>>(
            NTOK, HH, EHID, hmoeB, EHID,
            ew2 + (long long)l * EE * EHID * HH, HH,
            eb2 + (long long)l * EE * HH,
            ymoeB, HH, 1.f, 1,
            0, 0, (long long)EHID * HH, 0, 0, 0, (long long)HH,
            slotB, slotB, NTOK, cnt);

        moe_combine_k<<<NTOK, 256>>>(xb, ymoeB);
    }

    // --- LM head: NN, M=4096 N=32000 K=1024, TF32x2 (final op; no amplification) ---
    gemm_tc<false, 0, 2><<<dim3(250, 32, 1), 256, SMEM_BYTES>>>(
        NTOK, VV, HH, xb, HH, lmw, VV, lmb,
        out, VV, 1.f, 1, 0, 0, 0, 0, 0, 0, 0,
        nullptr, nullptr, 0, nullptr);
}